// round 1
// baseline (speedup 1.0000x reference)
#include <cuda_runtime.h>
#include <cstdint>

// ---------------------------------------------------------------------------
// Model_57183194578962 — fused neighbor-attention + cosine loss
// B=512, N=100, E=512, D_MODEL=1024, H=8, DEPTH=128, VOCAB=50000
//
// Key algebraic reductions:
//   * pooled uses only att rows 0,1 -> only 2 query rows per batch
//   * K/V = gather(P_k/P_v) + rank-4 pos correction, P = text_table @ W_top
//   * cand_emb @ proj_top folded into rank-4 Mc + bias cc
// ---------------------------------------------------------------------------

#define Bsz 512
#define Nn  100
#define Ee  512
#define DM  1024
#define Hh  8
#define DEPTH 128
#define MVOCAB 50000

// scratch (static device allocations — no cudaMalloc allowed)
__device__ float g_Pk[MVOCAB * DM];        // text_table @ Wk_top   [50000,1024]
__device__ float g_Pv[MVOCAB * DM];        // text_table @ Wv_top   [50000,1024]
__device__ float g_Xq[2 * Bsz * DM];       // x rows 0,1 per batch  [1024,1024]
__device__ float g_Q [2 * Bsz * DM];       // Q rows                [1024,1024]
__device__ float g_att[2 * Bsz * DM];      // attention output      [1024,1024]
__device__ float g_O [2 * Bsz * DM];       // att @ Wo + bo         [1024,1024]
__device__ float g_pool[Bsz * DM];         // max over the 2 rows   [512,1024]
__device__ float g_enc[Bsz * Ee];          // pooled @ proj_bot + cc[512,512]
__device__ float g_Mk[4 * DM], g_ck[DM];
__device__ float g_Mv[4 * DM], g_cv[DM];
__device__ float g_Mc[4 * Ee], g_cc[Ee];

// ---------------------------------------------------------------------------
// Tiny fused matmuls: M_out[c][n] = sum_k W4[c][k]*Wbot[k][n],
//                     c_out[n]   = sum_k b_in[k]*Wbot[k][n] + b_out[n]
// ---------------------------------------------------------------------------
__global__ void fuse_small(const float* __restrict__ W4, const float* __restrict__ b_in,
                           const float* __restrict__ Wbot, const float* __restrict__ b_out,
                           float* __restrict__ M_out, float* __restrict__ c_out,
                           int K2, int Nout, int ldb) {
    int n = blockIdx.x * blockDim.x + threadIdx.x;
    if (n >= Nout) return;
    float m0 = 0.f, m1 = 0.f, m2 = 0.f, m3 = 0.f, c = 0.f;
    for (int k = 0; k < K2; k++) {
        float w = Wbot[(size_t)k * ldb + n];
        m0 += W4[k] * w;
        m1 += W4[K2 + k] * w;
        m2 += W4[2 * K2 + k] * w;
        m3 += W4[3 * K2 + k] * w;
        c  += b_in[k] * w;
    }
    M_out[n] = m0; M_out[Nout + n] = m1;
    M_out[2 * Nout + n] = m2; M_out[3 * Nout + n] = m3;
    c_out[n] = c + b_out[n];
}

// ---------------------------------------------------------------------------
// Build the 2 query-input rows per batch: [text_emb | pos_emb]
// ---------------------------------------------------------------------------
__global__ void build_xq(const int* __restrict__ nt, const float* __restrict__ npos,
                         const float* __restrict__ text_table,
                         const float* __restrict__ pos_W, const float* __restrict__ pos_b,
                         float* __restrict__ Xq) {
    int r = blockIdx.x;               // 0..1023 = b*2 + i
    int b = r >> 1, i = r & 1;
    int id = nt[b * Nn + i];
    const float* trow = text_table + (size_t)id * Ee;
    const float* pp = npos + (size_t)(b * Nn + i) * 4;
    float p0 = pp[0], p1 = pp[1], p2 = pp[2], p3 = pp[3];
    float* xr = Xq + (size_t)r * DM;
    for (int j = threadIdx.x; j < Ee; j += blockDim.x) {
        xr[j] = trow[j];
        xr[Ee + j] = p0 * pos_W[j] + p1 * pos_W[Ee + j] + p2 * pos_W[2 * Ee + j]
                   + p3 * pos_W[3 * Ee + j] + pos_b[j];
    }
}

// ---------------------------------------------------------------------------
// Classic tiled SGEMM: C[M,N] = A[M,K] @ B[K,N] (+bias[n]); lda=K, ldb=N.
// BM=BN=128, BK=16, 256 threads, 8x8 per-thread tile.
// ---------------------------------------------------------------------------
__global__ void __launch_bounds__(256) sgemm_bias(
        const float* __restrict__ A, const float* __restrict__ B,
        float* __restrict__ C, const float* __restrict__ bias,
        int M, int N, int K) {
    __shared__ float As[16][128];
    __shared__ float Bs[16][128];
    int tid = threadIdx.x;
    int row0 = blockIdx.y * 128, col0 = blockIdx.x * 128;
    int tx = tid & 15, ty = tid >> 4;
    float acc[8][8] = {};

    for (int k0 = 0; k0 < K; k0 += 16) {
        #pragma unroll
        for (int i = 0; i < 2; i++) {
            int id = tid + i * 256;
            int ar = id >> 2, ac = (id & 3) << 2;
            float4 v = make_float4(0.f, 0.f, 0.f, 0.f);
            int gr = row0 + ar;
            if (gr < M) v = *(const float4*)(A + (size_t)gr * K + k0 + ac);
            As[ac + 0][ar] = v.x; As[ac + 1][ar] = v.y;
            As[ac + 2][ar] = v.z; As[ac + 3][ar] = v.w;
            int br = id >> 5, bc = (id & 31) << 2;
            float4 w = *(const float4*)(B + (size_t)(k0 + br) * N + col0 + bc);
            *(float4*)&Bs[br][bc] = w;
        }
        __syncthreads();
        #pragma unroll
        for (int kk = 0; kk < 16; kk++) {
            float a[8], bb[8];
            #pragma unroll
            for (int i = 0; i < 8; i++) a[i] = As[kk][ty * 8 + i];
            #pragma unroll
            for (int j = 0; j < 8; j++) bb[j] = Bs[kk][tx * 8 + j];
            #pragma unroll
            for (int i = 0; i < 8; i++)
                #pragma unroll
                for (int j = 0; j < 8; j++)
                    acc[i][j] += a[i] * bb[j];
        }
        __syncthreads();
    }
    #pragma unroll
    for (int i = 0; i < 8; i++) {
        int r = row0 + ty * 8 + i;
        if (r >= M) continue;
        #pragma unroll
        for (int j = 0; j < 8; j += 4) {
            int c = col0 + tx * 8 + j;
            float4 v;
            v.x = acc[i][j + 0]; v.y = acc[i][j + 1];
            v.z = acc[i][j + 2]; v.w = acc[i][j + 3];
            if (bias) {
                v.x += bias[c]; v.y += bias[c + 1];
                v.z += bias[c + 2]; v.w += bias[c + 3];
            }
            *(float4*)(C + (size_t)r * N + c) = v;
        }
    }
}

// ---------------------------------------------------------------------------
// Attention: one block per batch. K/V rows reconstructed on the fly:
//   k_n = P_k[ids[n]] + pos_n @ Mk + ck   (same for v via Mv/cv)
// Only q rows 0,1 computed. Output att[b*2+q][1024].
// ---------------------------------------------------------------------------
__global__ void __launch_bounds__(256) attention_kernel(
        const int* __restrict__ nt, const float* __restrict__ npos,
        const float* __restrict__ Q, const float* __restrict__ Pk,
        const float* __restrict__ Pv,
        const float* __restrict__ Mk, const float* __restrict__ ck,
        const float* __restrict__ Mv, const float* __restrict__ cv,
        float* __restrict__ att) {
    __shared__ float sq[2 * DM];      // queries
    __shared__ float sM[4 * DM];      // Mk then Mv
    __shared__ float sc[DM];          // ck then cv
    __shared__ float sS[2][Hh][Nn];   // scores -> probs
    __shared__ int   sid[Nn];
    __shared__ float spos[Nn][4];
    __shared__ float smk[Nn];         // padding mask (ids==0)

    int b = blockIdx.x, t = threadIdx.x;
    int warp = t >> 5, lane = t & 31;

    for (int n = t; n < Nn; n += 256) {
        int id = nt[b * Nn + n];
        sid[n] = id;
        smk[n] = (id == 0) ? 1.f : 0.f;
        float4 p = *(const float4*)(npos + (size_t)(b * Nn + n) * 4);
        spos[n][0] = p.x; spos[n][1] = p.y; spos[n][2] = p.z; spos[n][3] = p.w;
    }
    for (int j = t; j < 2 * DM; j += 256) sq[j] = Q[(size_t)b * 2 * DM + j];
    for (int j = t; j < 4 * DM; j += 256) sM[j] = Mk[j];
    for (int j = t; j < DM; j += 256) sc[j] = ck[j];
    __syncthreads();

    float mq0 = smk[0], mq1 = smk[1];
    const float scale = 0.08838834764831845f;   // 1/sqrt(128)

    // --- pass 1: scores ---
    for (int n = warp; n < Nn; n += 8) {
        const float* kr = Pk + (size_t)sid[n] * DM;
        float p0 = spos[n][0], p1 = spos[n][1], p2 = spos[n][2], p3 = spos[n][3];
        float mterm = smk[n];
        #pragma unroll
        for (int h = 0; h < Hh; h++) {
            int j = h * DEPTH + lane * 4;
            float4 k4 = *(const float4*)(kr + j);
            float kv[4] = {k4.x, k4.y, k4.z, k4.w};
            float d0 = 0.f, d1 = 0.f;
            #pragma unroll
            for (int u = 0; u < 4; u++) {
                int jj = j + u;
                float kk = kv[u] + p0 * sM[jj] + p1 * sM[DM + jj]
                         + p2 * sM[2 * DM + jj] + p3 * sM[3 * DM + jj] + sc[jj];
                d0 += kk * sq[jj];
                d1 += kk * sq[DM + jj];
            }
            #pragma unroll
            for (int off = 16; off; off >>= 1) {
                d0 += __shfl_xor_sync(0xffffffffu, d0, off);
                d1 += __shfl_xor_sync(0xffffffffu, d1, off);
            }
            if (lane == 0) {
                sS[0][h][n] = d0 * scale + mq0 * mterm * (-1e9f);
                sS[1][h][n] = d1 * scale + mq1 * mterm * (-1e9f);
            }
        }
    }
    __syncthreads();

    // --- softmax over n: 16 (q,h) rows, 2 per warp ---
    for (int r = warp; r < 16; r += 8) {
        float* row = &sS[r >> 3][r & 7][0];
        float mx = -1e30f;
        for (int jn = lane; jn < Nn; jn += 32) mx = fmaxf(mx, row[jn]);
        #pragma unroll
        for (int off = 16; off; off >>= 1)
            mx = fmaxf(mx, __shfl_xor_sync(0xffffffffu, mx, off));
        float ev[4]; int cnt = 0; float sum = 0.f;
        for (int jn = lane; jn < Nn; jn += 32) {
            float e = expf(row[jn] - mx);
            ev[cnt++] = e; sum += e;
        }
        #pragma unroll
        for (int off = 16; off; off >>= 1)
            sum += __shfl_xor_sync(0xffffffffu, sum, off);
        float inv = 1.f / sum;
        cnt = 0;
        for (int jn = lane; jn < Nn; jn += 32) row[jn] = ev[cnt++] * inv;
    }
    __syncthreads();

    // swap in Mv/cv
    for (int j = t; j < 4 * DM; j += 256) sM[j] = Mv[j];
    for (int j = t; j < DM; j += 256) sc[j] = cv[j];
    __syncthreads();

    // --- pass 2: att = probs @ V ---
    int d0i = t * 4;                 // 256 threads * 4 = 1024 dims
    int h = d0i >> 7;
    float a0[4] = {0, 0, 0, 0}, a1[4] = {0, 0, 0, 0};
    for (int n = 0; n < Nn; n++) {
        const float* vr = Pv + (size_t)sid[n] * DM;
        float4 v4 = *(const float4*)(vr + d0i);
        float vv[4] = {v4.x, v4.y, v4.z, v4.w};
        float p0 = spos[n][0], p1 = spos[n][1], p2 = spos[n][2], p3 = spos[n][3];
        float w0 = sS[0][h][n], w1 = sS[1][h][n];
        #pragma unroll
        for (int u = 0; u < 4; u++) {
            int jj = d0i + u;
            float v = vv[u] + p0 * sM[jj] + p1 * sM[DM + jj]
                    + p2 * sM[2 * DM + jj] + p3 * sM[3 * DM + jj] + sc[jj];
            a0[u] += w0 * v;
            a1[u] += w1 * v;
        }
    }
    *(float4*)(att + (size_t)b * 2 * DM + d0i)      = make_float4(a0[0], a0[1], a0[2], a0[3]);
    *(float4*)(att + (size_t)b * 2 * DM + DM + d0i) = make_float4(a1[0], a1[1], a1[2], a1[3]);
}

// ---------------------------------------------------------------------------
__global__ void pool_kernel(const float* __restrict__ O, float* __restrict__ pooled) {
    int idx = blockIdx.x * blockDim.x + threadIdx.x;
    if (idx >= Bsz * DM) return;
    int b = idx >> 10, k = idx & (DM - 1);
    pooled[idx] = fmaxf(O[(size_t)(2 * b) * DM + k], O[(size_t)(2 * b + 1) * DM + k]);
}

// ---------------------------------------------------------------------------
// Final: enc[b] += cand_pos[b] @ Mc ; cosine with field_table[field_id[b]]
// ---------------------------------------------------------------------------
__global__ void __launch_bounds__(128) cosine_kernel(
        const float* __restrict__ enc, const float* __restrict__ cand_pos,
        const float* __restrict__ Mc, const int* __restrict__ field_id,
        const float* __restrict__ field_table, float* __restrict__ out) {
    __shared__ float red[3][4];
    int b = blockIdx.x, t = threadIdx.x;
    int warp = t >> 5, lane = t & 31;
    const float* fp = field_table + (size_t)field_id[b] * Ee;
    float4 cp = *(const float4*)(cand_pos + (size_t)b * 4);
    float na = 0.f, nb = 0.f, dp = 0.f;
    for (int j = t; j < Ee; j += 128) {
        float e = enc[(size_t)b * Ee + j]
                + cp.x * Mc[j] + cp.y * Mc[Ee + j]
                + cp.z * Mc[2 * Ee + j] + cp.w * Mc[3 * Ee + j];
        float f = fp[j];
        na += e * e; nb += f * f; dp += e * f;
    }
    #pragma unroll
    for (int off = 16; off; off >>= 1) {
        na += __shfl_xor_sync(0xffffffffu, na, off);
        nb += __shfl_xor_sync(0xffffffffu, nb, off);
        dp += __shfl_xor_sync(0xffffffffu, dp, off);
    }
    if (lane == 0) { red[0][warp] = na; red[1][warp] = nb; red[2][warp] = dp; }
    __syncthreads();
    if (t == 0) {
        na = red[0][0] + red[0][1] + red[0][2] + red[0][3];
        nb = red[1][0] + red[1][1] + red[1][2] + red[1][3];
        dp = red[2][0] + red[2][1] + red[2][2] + red[2][3];
        out[b] = -dp * rsqrtf(fmaxf(na, 1e-12f)) * rsqrtf(fmaxf(nb, 1e-12f));
    }
}

// ---------------------------------------------------------------------------
extern "C" void kernel_launch(void* const* d_in, const int* in_sizes, int n_in,
                              void* d_out, int out_size) {
    const int*   field_id   = (const int*)  d_in[0];
    const float* cand_pos   = (const float*)d_in[1];
    const int*   nt         = (const int*)  d_in[2];
    const float* npos       = (const float*)d_in[3];
    const float* text_table = (const float*)d_in[4];
    const float* field_tab  = (const float*)d_in[5];
    const float* cand_W     = (const float*)d_in[6];
    const float* cand_b     = (const float*)d_in[7];
    const float* pos_W      = (const float*)d_in[8];
    const float* pos_b      = (const float*)d_in[9];
    const float* Wq         = (const float*)d_in[10];
    const float* bq         = (const float*)d_in[11];
    const float* Wk         = (const float*)d_in[12];
    const float* bk         = (const float*)d_in[13];
    const float* Wv         = (const float*)d_in[14];
    const float* bv         = (const float*)d_in[15];
    const float* Wo         = (const float*)d_in[16];
    const float* bo         = (const float*)d_in[17];
    const float* proj_W     = (const float*)d_in[18];
    const float* proj_b     = (const float*)d_in[19];
    float* out = (float*)d_out;

    float *Pk, *Pv, *Xq, *Qb, *attb, *Ob, *poolb, *encb;
    float *Mkp, *ckp, *Mvp, *cvp, *Mcp, *ccp;
    cudaGetSymbolAddress((void**)&Pk,   g_Pk);
    cudaGetSymbolAddress((void**)&Pv,   g_Pv);
    cudaGetSymbolAddress((void**)&Xq,   g_Xq);
    cudaGetSymbolAddress((void**)&Qb,   g_Q);
    cudaGetSymbolAddress((void**)&attb, g_att);
    cudaGetSymbolAddress((void**)&Ob,   g_O);
    cudaGetSymbolAddress((void**)&poolb,g_pool);
    cudaGetSymbolAddress((void**)&encb, g_enc);
    cudaGetSymbolAddress((void**)&Mkp,  g_Mk);
    cudaGetSymbolAddress((void**)&ckp,  g_ck);
    cudaGetSymbolAddress((void**)&Mvp,  g_Mv);
    cudaGetSymbolAddress((void**)&cvp,  g_cv);
    cudaGetSymbolAddress((void**)&Mcp,  g_Mc);
    cudaGetSymbolAddress((void**)&ccp,  g_cc);

    // rank-4 fusions
    fuse_small<<<4, 256>>>(pos_W, pos_b, Wk + (size_t)Ee * DM, bk, Mkp, ckp, Ee, DM, DM);
    fuse_small<<<4, 256>>>(pos_W, pos_b, Wv + (size_t)Ee * DM, bv, Mvp, cvp, Ee, DM, DM);
    fuse_small<<<2, 256>>>(cand_W, cand_b, proj_W, proj_b, Mcp, ccp, Ee, Ee, Ee);

    // query inputs (rows 0,1 only)
    build_xq<<<2 * Bsz, 256>>>(nt, npos, text_table, pos_W, pos_b, Xq);

    // dominant GEMMs: P_k/P_v = text_table @ W*_top  (M=50000, N=1024, K=512)
    dim3 gP(DM / 128, (MVOCAB + 127) / 128);
    sgemm_bias<<<gP, 256>>>(text_table, Wk, Pk, nullptr, MVOCAB, DM, Ee);
    sgemm_bias<<<gP, 256>>>(text_table, Wv, Pv, nullptr, MVOCAB, DM, Ee);

    // Q = Xq @ Wq + bq  (M=1024, N=1024, K=1024)
    sgemm_bias<<<dim3(8, 8), 256>>>(Xq, Wq, Qb, bq, 2 * Bsz, DM, DM);

    // attention (2 query rows per batch)
    attention_kernel<<<Bsz, 256>>>(nt, npos, Qb, Pk, Pv, Mkp, ckp, Mvp, cvp, attb);

    // O = att @ Wo + bo
    sgemm_bias<<<dim3(8, 8), 256>>>(attb, Wo, Ob, bo, 2 * Bsz, DM, DM);

    // pooled = max(O[2b], O[2b+1])
    pool_kernel<<<(Bsz * DM + 255) / 256, 256>>>(Ob, poolb);

    // enc = pooled @ proj_W[512:,:] + cc
    sgemm_bias<<<dim3(Ee / 128, Bsz / 128), 256>>>(poolb, proj_W + (size_t)Ee * Ee,
                                                   encb, ccp, Bsz, Ee, DM);

    // cosine loss
    cosine_kernel<<<Bsz, 128>>>(encb, cand_pos, Mcp, field_id, field_tab, out);
}

// round 4
// speedup vs baseline: 3.0717x; 3.0717x over previous
#include <cuda_runtime.h>
#include <cstdint>

// ---------------------------------------------------------------------------
// Model_57183194578962 — fused neighbor-attention + cosine loss
// B=512, N=100, E=512, D_MODEL=1024, H=8, DEPTH=128, VOCAB=50000
//
// Round 3: eliminate the vocab-sized GEMMs entirely.
//   scores: q·k = t_n·(Wk_h@q_h)_top + pos_n·r4 + c0      (gather-dot)
//   att:    Σ w_n v_n = (Σ w_n x_n)@Wv + bv               (weighted-sum first)
// Total FLOP ~8e9 fp32 instead of 1.1e11.
// ---------------------------------------------------------------------------

#define Bsz 512
#define Nn  100
#define Ee  512
#define DM  1024
#define Hh  8
#define DEPTH 128

// ------------------------- static scratch ----------------------------------
__device__ float g_Xq[2 * Bsz * DM];         // x rows 0,1 per batch   [1024,1024]
__device__ float g_Q [2 * Bsz * DM];         // Q rows                 [1024,1024]
__device__ float g_U [16 * Bsz * DM];        // u vectors  [(bq)*8+h][1024]
__device__ float g_r4[16 * Bsz * 4];         // pos_W @ u_bot per bqh
__device__ float g_c0[16 * Bsz];             // pos_b·u_bot + bk_h·q_h
__device__ float g_xbar[16 * Bsz * Ee];      // Σ w_n t_n  [(bq)*8+h][512]
__device__ float g_wpos[16 * Bsz * 4];       // Σ w_n pos_n
__device__ float g_att[2 * Bsz * DM];        // attention output       [1024,1024]
__device__ float g_O [2 * Bsz * DM];         // att @ Wo + bo
__device__ float g_pool[Bsz * DM];
__device__ float g_enc[Bsz * Ee];
__device__ float g_Mv[4 * DM], g_cv[DM];
__device__ float g_Mc[4 * Ee], g_cc[Ee];

// ---------------------------------------------------------------------------
// Tiny fused matmuls: M_out[c][n] = sum_k W4[c][k]*Wbot[k][n],
//                     c_out[n]   = sum_k b_in[k]*Wbot[k][n] + b_out[n]
// ---------------------------------------------------------------------------
__global__ void fuse_small(const float* __restrict__ W4, const float* __restrict__ b_in,
                           const float* __restrict__ Wbot, const float* __restrict__ b_out,
                           float* __restrict__ M_out, float* __restrict__ c_out,
                           int K2, int Nout, int ldb) {
    int n = blockIdx.x * blockDim.x + threadIdx.x;
    if (n >= Nout) return;
    float m0 = 0.f, m1 = 0.f, m2 = 0.f, m3 = 0.f, c = 0.f;
    for (int k = 0; k < K2; k++) {
        float w = Wbot[(size_t)k * ldb + n];
        m0 += W4[k] * w;
        m1 += W4[K2 + k] * w;
        m2 += W4[2 * K2 + k] * w;
        m3 += W4[3 * K2 + k] * w;
        c  += b_in[k] * w;
    }
    M_out[n] = m0; M_out[Nout + n] = m1;
    M_out[2 * Nout + n] = m2; M_out[3 * Nout + n] = m3;
    c_out[n] = c + b_out[n];
}

// ---------------------------------------------------------------------------
// Build the 2 query-input rows per batch: [text_emb | pos_emb]
// ---------------------------------------------------------------------------
__global__ void build_xq(const int* __restrict__ nt, const float* __restrict__ npos,
                         const float* __restrict__ text_table,
                         const float* __restrict__ pos_W, const float* __restrict__ pos_b,
                         float* __restrict__ Xq) {
    int r = blockIdx.x;               // 0..1023 = b*2 + i
    int b = r >> 1, i = r & 1;
    int id = nt[b * Nn + i];
    const float* trow = text_table + (size_t)id * Ee;
    const float* pp = npos + (size_t)(b * Nn + i) * 4;
    float p0 = pp[0], p1 = pp[1], p2 = pp[2], p3 = pp[3];
    float* xr = Xq + (size_t)r * DM;
    for (int j = threadIdx.x; j < Ee; j += blockDim.x) {
        xr[j] = trow[j];
        xr[Ee + j] = p0 * pos_W[j] + p1 * pos_W[Ee + j] + p2 * pos_W[2 * Ee + j]
                   + p3 * pos_W[3 * Ee + j] + pos_b[j];
    }
}

// ---------------------------------------------------------------------------
// Classic tiled SGEMM: C[M,N] = A[M,K] @ B[K,N] (+bias[n]); lda=K, ldb=N.
// ---------------------------------------------------------------------------
__global__ void __launch_bounds__(256) sgemm_bias(
        const float* __restrict__ A, const float* __restrict__ B,
        float* __restrict__ C, const float* __restrict__ bias,
        int M, int N, int K) {
    __shared__ float As[16][128];
    __shared__ float Bs[16][128];
    int tid = threadIdx.x;
    int row0 = blockIdx.y * 128, col0 = blockIdx.x * 128;
    int tx = tid & 15, ty = tid >> 4;
    float acc[8][8] = {};

    for (int k0 = 0; k0 < K; k0 += 16) {
        #pragma unroll
        for (int i = 0; i < 2; i++) {
            int id = tid + i * 256;
            int ar = id >> 2, ac = (id & 3) << 2;
            float4 v = make_float4(0.f, 0.f, 0.f, 0.f);
            int gr = row0 + ar;
            if (gr < M) v = *(const float4*)(A + (size_t)gr * K + k0 + ac);
            As[ac + 0][ar] = v.x; As[ac + 1][ar] = v.y;
            As[ac + 2][ar] = v.z; As[ac + 3][ar] = v.w;
            int br = id >> 5, bc = (id & 31) << 2;
            float4 w = *(const float4*)(B + (size_t)(k0 + br) * N + col0 + bc);
            *(float4*)&Bs[br][bc] = w;
        }
        __syncthreads();
        #pragma unroll
        for (int kk = 0; kk < 16; kk++) {
            float a[8], bb[8];
            #pragma unroll
            for (int i = 0; i < 8; i++) a[i] = As[kk][ty * 8 + i];
            #pragma unroll
            for (int j = 0; j < 8; j++) bb[j] = Bs[kk][tx * 8 + j];
            #pragma unroll
            for (int i = 0; i < 8; i++)
                #pragma unroll
                for (int j = 0; j < 8; j++)
                    acc[i][j] += a[i] * bb[j];
        }
        __syncthreads();
    }
    #pragma unroll
    for (int i = 0; i < 8; i++) {
        int r = row0 + ty * 8 + i;
        if (r >= M) continue;
        #pragma unroll
        for (int j = 0; j < 8; j += 4) {
            int c = col0 + tx * 8 + j;
            float4 v;
            v.x = acc[i][j + 0]; v.y = acc[i][j + 1];
            v.z = acc[i][j + 2]; v.w = acc[i][j + 3];
            if (bias) {
                v.x += bias[c]; v.y += bias[c + 1];
                v.z += bias[c + 2]; v.w += bias[c + 3];
            }
            *(float4*)(C + (size_t)r * N + c) = v;
        }
    }
}

// ---------------------------------------------------------------------------
// U GEMM (batched over h, NT):  U[(bq)*8+h][i] = sum_{d<128} Q[bq, h*128+d] * Wk[i, h*128+d]
// grid (8 col-tiles, 8 row-tiles, 8 h); tile 128x128, BK=16.
// ---------------------------------------------------------------------------
__global__ void __launch_bounds__(256) sgemm_u_nt(
        const float* __restrict__ Q, const float* __restrict__ Wk,
        float* __restrict__ U) {
    __shared__ float As[16][128];
    __shared__ float Bs[16][128];
    int tid = threadIdx.x;
    int col0 = blockIdx.x * 128, row0 = blockIdx.y * 128, z = blockIdx.z;
    int tx = tid & 15, ty = tid >> 4;
    float acc[8][8] = {};

    for (int k0 = 0; k0 < 128; k0 += 16) {
        // A tile: Q[row0+r, z*128 + k0 + d]
        #pragma unroll
        for (int i = 0; i < 2; i++) {
            int id = tid + i * 256;
            int ar = id >> 2, ac = (id & 3) << 2;
            float4 v = *(const float4*)(Q + (size_t)(row0 + ar) * DM + z * 128 + k0 + ac);
            As[ac + 0][ar] = v.x; As[ac + 1][ar] = v.y;
            As[ac + 2][ar] = v.z; As[ac + 3][ar] = v.w;
        }
        // B tile (transposed read): Wk[col0+i, z*128 + k0 + d] -> Bs[d][i]
        #pragma unroll
        for (int p = 0; p < 2; p++) {
            int i = (tid >> 2) + p * 64;
            int dq = (tid & 3) << 2;
            float4 v = *(const float4*)(Wk + (size_t)(col0 + i) * DM + z * 128 + k0 + dq);
            Bs[dq + 0][i] = v.x; Bs[dq + 1][i] = v.y;
            Bs[dq + 2][i] = v.z; Bs[dq + 3][i] = v.w;
        }
        __syncthreads();
        #pragma unroll
        for (int kk = 0; kk < 16; kk++) {
            float a[8], bb[8];
            #pragma unroll
            for (int i = 0; i < 8; i++) a[i] = As[kk][ty * 8 + i];
            #pragma unroll
            for (int j = 0; j < 8; j++) bb[j] = Bs[kk][tx * 8 + j];
            #pragma unroll
            for (int i = 0; i < 8; i++)
                #pragma unroll
                for (int j = 0; j < 8; j++)
                    acc[i][j] += a[i] * bb[j];
        }
        __syncthreads();
    }
    // C: U[((row0+r)*8 + z)*1024 + col0 + c]
    #pragma unroll
    for (int i = 0; i < 8; i++) {
        int r = row0 + ty * 8 + i;
        float* dst = U + ((size_t)r * 8 + z) * DM + col0 + tx * 8;
        #pragma unroll
        for (int j = 0; j < 8; j += 4)
            *(float4*)(dst + j) = make_float4(acc[i][j], acc[i][j + 1],
                                              acc[i][j + 2], acc[i][j + 3]);
    }
}

// ---------------------------------------------------------------------------
// Per-(bq,h) score constants: r4 = pos_W @ u_bot, c0 = pos_b·u_bot + bk_h·q_h
// One warp per row i.
// ---------------------------------------------------------------------------
__global__ void __launch_bounds__(256) score_consts(
        const float* __restrict__ U, const float* __restrict__ Q,
        const float* __restrict__ pos_W, const float* __restrict__ pos_b,
        const float* __restrict__ bk,
        float* __restrict__ r4, float* __restrict__ c0) {
    int warp = threadIdx.x >> 5, lane = threadIdx.x & 31;
    int i = blockIdx.x * 8 + warp;          // 0..8191
    int bq = i >> 3, h = i & 7;
    const float* ub = U + (size_t)i * DM + Ee;
    #pragma unroll
    for (int c = 0; c < 4; c++) {
        float s = 0.f;
        for (int d = lane; d < Ee; d += 32) s += pos_W[c * Ee + d] * ub[d];
        #pragma unroll
        for (int off = 16; off; off >>= 1) s += __shfl_xor_sync(0xffffffffu, s, off);
        if (lane == 0) r4[i * 4 + c] = s;
    }
    float s = 0.f;
    for (int d = lane; d < Ee; d += 32) s += pos_b[d] * ub[d];
    for (int d = lane; d < DEPTH; d += 32)
        s += bk[h * DEPTH + d] * Q[(size_t)bq * DM + h * DEPTH + d];
    #pragma unroll
    for (int off = 16; off; off >>= 1) s += __shfl_xor_sync(0xffffffffu, s, off);
    if (lane == 0) c0[i] = s;
}

// ---------------------------------------------------------------------------
// Fused attention: scores (gather-dot) -> softmax -> xbar (gather-axpy), per batch.
// Dynamic smem layout (floats):
//   [0,8192)      sUt[512][16]    (phase A)  /  sT2[16][512], sX[16][512] (phase C/D)
//   [8192,11492)  sT[100][33]     (phase A staging)
//   [11492,13156) sS[16][104]
//   [13156,13556) spos[100][4]
//   [13556,13620) sr4[16][4]
//   [13620,13636) sc0[16]
//   [13636,13736) sid[100] (int)
// ---------------------------------------------------------------------------
#define ATTN_SMEM (13736 * 4)

__global__ void __launch_bounds__(256) attn_fused(
        const int* __restrict__ nt, const float* __restrict__ npos,
        const float* __restrict__ U, const float* __restrict__ r4,
        const float* __restrict__ c0, const float* __restrict__ text_table,
        float* __restrict__ xbar, float* __restrict__ wpos) {
    extern __shared__ float dyn[];
    float* sUt  = dyn;                  // [512][16] transposed u_top
    float* sT   = dyn + 8192;           // [100][33]
    float* sS   = dyn + 11492;          // [16][104]
    float* spos = dyn + 13156;          // [100][4]
    float* sr4  = dyn + 13556;          // [16][4]
    float* sc0  = dyn + 13620;          // [16]
    int*   sid  = (int*)(dyn + 13636);  // [100]

    int b = blockIdx.x, tid = threadIdx.x;
    int warp = tid >> 5, lane = tid & 31;

    // ---- stage per-batch inputs ----
    for (int n = tid; n < Nn; n += 256) {
        int id = nt[b * Nn + n];
        sid[n] = id;
        float4 p = *(const float4*)(npos + (size_t)(b * Nn + n) * 4);
        spos[n * 4 + 0] = p.x; spos[n * 4 + 1] = p.y;
        spos[n * 4 + 2] = p.z; spos[n * 4 + 3] = p.w;
    }
    for (int idx = tid; idx < 16 * Ee; idx += 256) {
        int qh = idx >> 9, d = idx & 511;
        sUt[d * 16 + qh] = U[((size_t)b * 16 + qh) * DM + d];
    }
    for (int idx = tid; idx < 64; idx += 256) sr4[idx] = r4[(size_t)b * 64 + idx];
    if (tid < 16) sc0[tid] = c0[(size_t)b * 16 + tid];
    __syncthreads();

    float m0 = (sid[0] == 0) ? 1.f : 0.f;
    float m1 = (sid[1] == 0) ? 1.f : 0.f;
    const float scale = 0.08838834764831845f;   // 1/sqrt(128)

    // ---- phase A: scores = t_n · u_top ----
    // 200 active threads: (qh pair, n quad)
    bool active = tid < 200;
    int qh0 = (tid & 7) * 2;
    int n0 = (tid >> 3) * 4;
    float acc[2][4] = {};

    for (int kc = 0; kc < 16; kc++) {
        for (int idx = tid; idx < Nn * 32; idx += 256) {
            int n = idx >> 5, d = idx & 31;
            sT[n * 33 + d] = text_table[(size_t)sid[n] * Ee + kc * 32 + d];
        }
        __syncthreads();
        if (active) {
            #pragma unroll
            for (int d = 0; d < 32; d++) {
                int gd = kc * 32 + d;
                float2 u2 = *(float2*)&sUt[gd * 16 + qh0];
                #pragma unroll
                for (int i = 0; i < 4; i++) {
                    float t = sT[(n0 + i) * 33 + d];
                    acc[0][i] += u2.x * t;
                    acc[1][i] += u2.y * t;
                }
            }
        }
        __syncthreads();
    }
    if (active) {
        #pragma unroll
        for (int j = 0; j < 2; j++) {
            int qh = qh0 + j;
            float mq = (qh < 8) ? m0 : m1;
            #pragma unroll
            for (int i = 0; i < 4; i++) {
                int n = n0 + i;
                float s = acc[j][i]
                        + spos[n * 4 + 0] * sr4[qh * 4 + 0]
                        + spos[n * 4 + 1] * sr4[qh * 4 + 1]
                        + spos[n * 4 + 2] * sr4[qh * 4 + 2]
                        + spos[n * 4 + 3] * sr4[qh * 4 + 3]
                        + sc0[qh];
                float mn = (sid[n] == 0) ? 1.f : 0.f;
                sS[qh * 104 + n] = s * scale + mq * mn * (-1e9f);
            }
        }
    }
    __syncthreads();

    // ---- phase B: softmax over n per (qh) row ----
    for (int r = warp; r < 16; r += 8) {
        float* row = sS + r * 104;
        float mx = -1e30f;
        for (int jn = lane; jn < Nn; jn += 32) mx = fmaxf(mx, row[jn]);
        #pragma unroll
        for (int off = 16; off; off >>= 1)
            mx = fmaxf(mx, __shfl_xor_sync(0xffffffffu, mx, off));
        float ev[4]; int cnt = 0; float sum = 0.f;
        for (int jn = lane; jn < Nn; jn += 32) {
            float e = expf(row[jn] - mx);
            ev[cnt++] = e; sum += e;
        }
        #pragma unroll
        for (int off = 16; off; off >>= 1)
            sum += __shfl_xor_sync(0xffffffffu, sum, off);
        float inv = 1.f / sum;
        cnt = 0;
        for (int jn = lane; jn < Nn; jn += 32) row[jn] = ev[cnt++] * inv;
    }
    __syncthreads();

    // ---- wpos = sum_n w * pos ----
    if (tid < 64) {
        int qh = tid >> 2, c = tid & 3;
        float s = 0.f;
        for (int n = 0; n < Nn; n++) s += sS[qh * 104 + n] * spos[n * 4 + c];
        wpos[((size_t)b * 16 + qh) * 4 + c] = s;
    }

    // ---- phase C: xbar[qh][512] = sum_n w[qh][n] * t_n ----
    float* sT2 = dyn;                   // reuse [16][512]
    int qh = tid & 15, dg = tid >> 4;   // dims d = dg + 16*j
    float xa[32] = {};
    for (int nc = 0; nc < 7; nc++) {
        __syncthreads();
        for (int idx = tid; idx < 16 * Ee; idx += 256) {
            int rr = idx >> 9, d = idx & 511;
            int n = nc * 16 + rr;
            if (n < Nn) sT2[rr * Ee + d] = text_table[(size_t)sid[n] * Ee + d];
        }
        __syncthreads();
        int nmax = min(16, Nn - nc * 16);
        for (int rr = 0; rr < nmax; rr++) {
            float w = sS[qh * 104 + nc * 16 + rr];
            const float* tp = sT2 + rr * Ee + dg;
            #pragma unroll
            for (int j = 0; j < 32; j++) xa[j] += w * tp[16 * j];
        }
    }
    // ---- phase D: stage + coalesced write ----
    __syncthreads();
    float* sX = dyn;                    // reuse [16][512]
    #pragma unroll
    for (int j = 0; j < 32; j++) sX[qh * Ee + dg + 16 * j] = xa[j];
    __syncthreads();
    for (int idx = tid; idx < 16 * Ee; idx += 256) {
        int q2 = idx >> 9, d = idx & 511;
        xbar[((size_t)b * 16 + q2) * Ee + d] = sX[idx];
    }
}

// ---------------------------------------------------------------------------
// att GEMM (batched over h): att[bq, z*128+j] = sum_k xbar[(bq)*8+z][k]*Wv[k, z*128+j]
//                            + wpos[(bq)*8+z]·Mv[:, z*128+j] + cv[z*128+j]
// grid (8 row tiles, 8 z); tile 128x128, K=512.
// ---------------------------------------------------------------------------
__global__ void __launch_bounds__(256) sgemm_att(
        const float* __restrict__ xbar, const float* __restrict__ Wv,
        const float* __restrict__ wpos, const float* __restrict__ Mv,
        const float* __restrict__ cv, float* __restrict__ att) {
    __shared__ float As[16][128];
    __shared__ float Bs[16][128];
    int tid = threadIdx.x;
    int row0 = blockIdx.x * 128, z = blockIdx.y;
    int tx = tid & 15, ty = tid >> 4;
    float acc[8][8] = {};

    for (int k0 = 0; k0 < Ee; k0 += 16) {
        #pragma unroll
        for (int i = 0; i < 2; i++) {
            int id = tid + i * 256;
            int ar = id >> 2, ac = (id & 3) << 2;
            float4 v = *(const float4*)(xbar + (size_t)(row0 + ar) * (8 * Ee)
                                        + z * Ee + k0 + ac);
            As[ac + 0][ar] = v.x; As[ac + 1][ar] = v.y;
            As[ac + 2][ar] = v.z; As[ac + 3][ar] = v.w;
            int br = id >> 5, bc = (id & 31) << 2;
            float4 w = *(const float4*)(Wv + (size_t)(k0 + br) * DM + z * 128 + bc);
            *(float4*)&Bs[br][bc] = w;
        }
        __syncthreads();
        #pragma unroll
        for (int kk = 0; kk < 16; kk++) {
            float a[8], bb[8];
            #pragma unroll
            for (int i = 0; i < 8; i++) a[i] = As[kk][ty * 8 + i];
            #pragma unroll
            for (int j = 0; j < 8; j++) bb[j] = Bs[kk][tx * 8 + j];
            #pragma unroll
            for (int i = 0; i < 8; i++)
                #pragma unroll
                for (int j = 0; j < 8; j++)
                    acc[i][j] += a[i] * bb[j];
        }
        __syncthreads();
    }
    #pragma unroll
    for (int i = 0; i < 8; i++) {
        int r = row0 + ty * 8 + i;
        const float* wp = wpos + ((size_t)r * 8 + z) * 4;
        float w0 = wp[0], w1 = wp[1], w2 = wp[2], w3 = wp[3];
        #pragma unroll
        for (int j = 0; j < 8; j += 4) {
            int cb = z * 128 + tx * 8 + j;
            float4 v;
            v.x = acc[i][j + 0]; v.y = acc[i][j + 1];
            v.z = acc[i][j + 2]; v.w = acc[i][j + 3];
            #pragma unroll
            for (int u = 0; u < 4; u++) {
                float e = cv[cb + u]
                        + w0 * Mv[0 * DM + cb + u] + w1 * Mv[1 * DM + cb + u]
                        + w2 * Mv[2 * DM + cb + u] + w3 * Mv[3 * DM + cb + u];
                (&v.x)[u] += e;
            }
            *(float4*)(att + (size_t)r * DM + cb) = v;
        }
    }
}

// ---------------------------------------------------------------------------
__global__ void pool_kernel(const float* __restrict__ O, float* __restrict__ pooled) {
    int idx = blockIdx.x * blockDim.x + threadIdx.x;
    if (idx >= Bsz * DM) return;
    int b = idx >> 10, k = idx & (DM - 1);
    pooled[idx] = fmaxf(O[(size_t)(2 * b) * DM + k], O[(size_t)(2 * b + 1) * DM + k]);
}

// ---------------------------------------------------------------------------
__global__ void __launch_bounds__(128) cosine_kernel(
        const float* __restrict__ enc, const float* __restrict__ cand_pos,
        const float* __restrict__ Mc, const int* __restrict__ field_id,
        const float* __restrict__ field_table, float* __restrict__ out) {
    __shared__ float red[3][4];
    int b = blockIdx.x, t = threadIdx.x;
    int warp = t >> 5, lane = t & 31;
    const float* fp = field_table + (size_t)field_id[b] * Ee;
    float4 cp = *(const float4*)(cand_pos + (size_t)b * 4);
    float na = 0.f, nb = 0.f, dp = 0.f;
    for (int j = t; j < Ee; j += 128) {
        float e = enc[(size_t)b * Ee + j]
                + cp.x * Mc[j] + cp.y * Mc[Ee + j]
                + cp.z * Mc[2 * Ee + j] + cp.w * Mc[3 * Ee + j];
        float f = fp[j];
        na += e * e; nb += f * f; dp += e * f;
    }
    #pragma unroll
    for (int off = 16; off; off >>= 1) {
        na += __shfl_xor_sync(0xffffffffu, na, off);
        nb += __shfl_xor_sync(0xffffffffu, nb, off);
        dp += __shfl_xor_sync(0xffffffffu, dp, off);
    }
    if (lane == 0) { red[0][warp] = na; red[1][warp] = nb; red[2][warp] = dp; }
    __syncthreads();
    if (t == 0) {
        na = red[0][0] + red[0][1] + red[0][2] + red[0][3];
        nb = red[1][0] + red[1][1] + red[1][2] + red[1][3];
        dp = red[2][0] + red[2][1] + red[2][2] + red[2][3];
        out[b] = -dp * rsqrtf(fmaxf(na, 1e-12f)) * rsqrtf(fmaxf(nb, 1e-12f));
    }
}

// ---------------------------------------------------------------------------
extern "C" void kernel_launch(void* const* d_in, const int* in_sizes, int n_in,
                              void* d_out, int out_size) {
    const int*   field_id   = (const int*)  d_in[0];
    const float* cand_pos   = (const float*)d_in[1];
    const int*   nt         = (const int*)  d_in[2];
    const float* npos       = (const float*)d_in[3];
    const float* text_table = (const float*)d_in[4];
    const float* field_tab  = (const float*)d_in[5];
    const float* cand_W     = (const float*)d_in[6];
    const float* cand_b     = (const float*)d_in[7];
    const float* pos_W      = (const float*)d_in[8];
    const float* pos_b      = (const float*)d_in[9];
    const float* Wq         = (const float*)d_in[10];
    const float* bq         = (const float*)d_in[11];
    const float* Wk         = (const float*)d_in[12];
    const float* bk         = (const float*)d_in[13];
    const float* Wv         = (const float*)d_in[14];
    const float* bv         = (const float*)d_in[15];
    const float* Wo         = (const float*)d_in[16];
    const float* bo         = (const float*)d_in[17];
    const float* proj_W     = (const float*)d_in[18];
    const float* proj_b     = (const float*)d_in[19];
    float* out = (float*)d_out;

    float *Xq, *Qb, *Ub, *r4b, *c0b, *xbarb, *wposb, *attb, *Ob, *poolb, *encb;
    float *Mvp, *cvp, *Mcp, *ccp;
    cudaGetSymbolAddress((void**)&Xq,    g_Xq);
    cudaGetSymbolAddress((void**)&Qb,    g_Q);
    cudaGetSymbolAddress((void**)&Ub,    g_U);
    cudaGetSymbolAddress((void**)&r4b,   g_r4);
    cudaGetSymbolAddress((void**)&c0b,   g_c0);
    cudaGetSymbolAddress((void**)&xbarb, g_xbar);
    cudaGetSymbolAddress((void**)&wposb, g_wpos);
    cudaGetSymbolAddress((void**)&attb,  g_att);
    cudaGetSymbolAddress((void**)&Ob,    g_O);
    cudaGetSymbolAddress((void**)&poolb, g_pool);
    cudaGetSymbolAddress((void**)&encb,  g_enc);
    cudaGetSymbolAddress((void**)&Mvp,   g_Mv);
    cudaGetSymbolAddress((void**)&cvp,   g_cv);
    cudaGetSymbolAddress((void**)&Mcp,   g_Mc);
    cudaGetSymbolAddress((void**)&ccp,   g_cc);

    cudaFuncSetAttribute(attn_fused,
                         cudaFuncAttributeMaxDynamicSharedMemorySize, ATTN_SMEM);

    // rank-4 fusions: Mv = pos_W @ Wv_bot, cv = pos_b @ Wv_bot + bv
    fuse_small<<<4, 256>>>(pos_W, pos_b, Wv + (size_t)Ee * DM, bv, Mvp, cvp, Ee, DM, DM);
    // Mc = cand_W @ proj_top, cc = cand_b @ proj_top + proj_b
    fuse_small<<<2, 256>>>(cand_W, cand_b, proj_W, proj_b, Mcp, ccp, Ee, Ee, Ee);

    // query inputs (rows 0,1 only)
    build_xq<<<2 * Bsz, 256>>>(nt, npos, text_table, pos_W, pos_b, Xq);

    // Q = Xq @ Wq + bq  (1024 x 1024 x 1024)
    sgemm_bias<<<dim3(8, 8), 256>>>(Xq, Wq, Qb, bq, 2 * Bsz, DM, DM);

    // U[(bq)*8+h] = Wk_h @ q_h  (8 x [1024 x 1024 x 128] NT)
    sgemm_u_nt<<<dim3(8, 8, 8), 256>>>(Qb, Wk, Ub);

    // per-(bq,h) score constants
    score_consts<<<16 * Bsz / 8, 256>>>(Ub, Qb, pos_W, pos_b, bk, r4b, c0b);

    // fused gather-scores -> softmax -> xbar/wpos
    attn_fused<<<Bsz, 256, ATTN_SMEM>>>(nt, npos, Ub, r4b, c0b, text_table,
                                        xbarb, wposb);

    // att = xbar @ Wv_top + wpos @ Mv + cv  (8 x [1024 x 128 x 512])
    sgemm_att<<<dim3(8, 8), 256>>>(xbarb, Wv, wposb, Mvp, cvp, attb);

    // O = att @ Wo + bo
    sgemm_bias<<<dim3(8, 8), 256>>>(attb, Wo, Ob, bo, 2 * Bsz, DM, DM);

    // pooled = max(O[2b], O[2b+1])
    pool_kernel<<<(Bsz * DM + 255) / 256, 256>>>(Ob, poolb);

    // enc = pooled @ proj_W[512:,:] + cc
    sgemm_bias<<<dim3(Ee / 128, Bsz / 128), 256>>>(poolb, proj_W + (size_t)Ee * Ee,
                                                   encb, ccp, Bsz, Ee, DM);

    // cosine loss
    cosine_kernel<<<Bsz, 128>>>(encb, cand_pos, Mcp, field_id, field_tab, out);
}